// round 16
// baseline (speedup 1.0000x reference)
#include <cuda_runtime.h>
#include <cuda_fp16.h>
#include <cstdint>

#define C1 64
#define C2 128
#define C3 256
#define DD 128
#define TM 128
#define NTHR 256

// ---------------- static device scratch (no allocs allowed) ----------------
__device__ __half g_y2h[(size_t)131072 * DD];    // level-2 merged features (fp16)
__device__ __half g_y3h[(size_t)30720 * DD];     // y3 = feats3 @ W3 (fp16)
__device__ int    g_perm1[420000 + 4096];
__device__ int    g_perm2[131072 + 4096];
__device__ __half g_B3h[8 * 8 * 4096];           // [bin][chunk][n][k swizzled] fp16
__device__ __half g_B2h[8 * 6 * 4096];
__device__ __half g_Bw3h[8 * 4096];              // W3 chunks for y3 GEMM
__device__ int    g_bh[32768];                   // bucket hist: [lvl][bin][2048]
__device__ int    g_bst[32768];                  // bucket start cursors
__device__ int    g_done;                        // prep completion counter
__device__ int    g_st1[9], g_st2[9];
__device__ int    g_cnt1[8], g_cnt2[8];

// ---------------- helpers ----------------
__device__ __forceinline__ uint32_t smem_u32(const void* p) {
    uint32_t a;
    asm("{ .reg .u64 t; cvta.to.shared.u64 t, %1; cvt.u32.u64 %0, t; }" : "=r"(a) : "l"(p));
    return a;
}
// B staging: L2-only (cg) — B is read once per CTA and shared via L2; keep it out of L1
__device__ __forceinline__ void cp16cg(void* dst_smem, const void* src) {
    uint32_t d = smem_u32(dst_smem);
    asm volatile("cp.async.cg.shared.global [%0], [%1], 16;" :: "r"(d), "l"(src) : "memory");
}
// A gather: L1-cached (ca) with zero-fill; gather lines have cross-row reuse in L1
__device__ __forceinline__ void cp16z(void* dst_smem, const void* src, uint32_t srcsize) {
    uint32_t d = smem_u32(dst_smem);
    asm volatile("cp.async.ca.shared.global [%0], [%1], 16, %2;"
                 :: "r"(d), "l"(src), "r"(srcsize) : "memory");
}
__device__ __forceinline__ void cp_commit() { asm volatile("cp.async.commit_group;" ::: "memory"); }
__device__ __forceinline__ void cp_wait2()  { asm volatile("cp.async.wait_group 2;" ::: "memory"); }
__device__ __forceinline__ void cp_wait1()  { asm volatile("cp.async.wait_group 1;" ::: "memory"); }
__device__ __forceinline__ void cp_wait0()  { asm volatile("cp.async.wait_group 0;" ::: "memory"); }

__device__ __forceinline__ uint32_t pk(float a, float b) {
    __half2 h = __floats2half2_rn(a, b);
    return *(uint32_t*)&h;
}
__device__ __forceinline__ void ldsm4(uint32_t* r, uint32_t addr) {
    asm volatile("ldmatrix.sync.aligned.m8n8.x4.shared.b16 {%0,%1,%2,%3}, [%4];"
                 : "=r"(r[0]), "=r"(r[1]), "=r"(r[2]), "=r"(r[3]) : "r"(addr));
}
__device__ __forceinline__ void mma_f16(float* c, const uint32_t* a, const uint32_t* b) {
    asm volatile(
        "mma.sync.aligned.m16n8k16.row.col.f32.f16.f16.f32 "
        "{%0,%1,%2,%3}, {%4,%5,%6,%7}, {%8,%9}, {%0,%1,%2,%3};\n"
        : "+f"(c[0]), "+f"(c[1]), "+f"(c[2]), "+f"(c[3])
        : "r"(a[0]), "r"(a[1]), "r"(a[2]), "r"(a[3]), "r"(b[0]), "r"(b[1]));
}

// swizzled half-index within a row-chunk tile (rows of 64B, XOR on 16B blocks)
__device__ __forceinline__ int swz_pos(int row, int kc) {
    return row * 32 + ((((kc >> 3) & 3) ^ ((row >> 1) & 3)) << 3) + (kc & 7);
}

__device__ __forceinline__ int bkt1(int off, int par) {
    int b = par >> 6; if (b > 2047) b = 2047;
    return (off << 11) | b;
}
__device__ __forceinline__ int bkt2(int off, int par) {
    int b = par >> 4; if (b > 2047) b = 2047;
    return 16384 + ((off << 11) | b);
}

// ---------------- prep: W3 tiles + bucket hist + fused last-block scan ----------------
__global__ void k_prep(const int* __restrict__ off1, const int* __restrict__ par1, int n1,
                       const int* __restrict__ off2, const int* __restrict__ par2, int n2,
                       const float* __restrict__ W3, __half* Bw3h,
                       int* st1, int* cnt1, int* st2, int* cnt2) {
    __shared__ int s_last;
    int i = blockIdx.x * blockDim.x + threadIdx.x;
    int stride = gridDim.x * blockDim.x;
    for (int j = i; j < 256 * 128; j += stride) {
        int k = j >> 7, n = j & 127;
        int ch = k >> 5, kc = k & 31;
        Bw3h[ch * 4096 + swz_pos(n, kc)] = __float2half_rn(W3[(size_t)k * 128 + n]);
    }
    // bucket histogram (RED atomics, spread addresses)
    for (int j = i; j < n1; j += stride) atomicAdd(&g_bh[bkt1(off1[j], par1[j])], 1);
    for (int j = i; j < n2; j += stride) atomicAdd(&g_bh[bkt2(off2[j], par2[j])], 1);
    __threadfence();
    __syncthreads();
    if (threadIdx.x == 0)
        s_last = (atomicAdd(&g_done, 1) == (int)gridDim.x - 1) ? 1 : 0;
    __syncthreads();
    if (s_last) {
        __threadfence();
        // fused scan: 16 (lvl,bin) groups x 16 segment-threads x 128 buckets
        __shared__ int seg[16][17];
        __shared__ int bstart[16];
        const int tid = threadIdx.x;
        const int gidx = tid >> 4, l = tid & 15;
        const int base = gidx * 2048 + l * 128;
        int s = 0;
        for (int j = 0; j < 128; j++) s += g_bh[base + j];
        seg[gidx][l] = s;
        __syncthreads();
        if (l == 0) {
            int run = 0;
            for (int j = 0; j < 16; j++) { int v = seg[gidx][j]; seg[gidx][j] = run; run += v; }
            seg[gidx][16] = run;                 // bin total
        }
        __syncthreads();
        if (tid == 0) {
            int run = 0;
            for (int k = 0; k < 8; k++) {
                st1[k] = run; cnt1[k] = seg[k][16]; bstart[k] = run;
                run += ((seg[k][16] + TM - 1) / TM) * TM;
            }
            st1[8] = run;
            run = 0;
            for (int k = 0; k < 8; k++) {
                st2[k] = run; cnt2[k] = seg[8 + k][16]; bstart[8 + k] = run;
                run += ((seg[8 + k][16] + TM - 1) / TM) * TM;
            }
            st2[8] = run;
            g_done = 0;                          // reset for next graph replay
        }
        __syncthreads();
        // bucket starts + zero hist for next replay
        int run2 = bstart[gidx] + seg[gidx][l];
        for (int j = 0; j < 128; j++) {
            int v = g_bh[base + j];
            g_bst[base + j] = run2;
            g_bh[base + j] = 0;
            run2 += v;
        }
    }
}

// merged: bucket-clustered scatter + build fp16 B tiles + pad-fill (last block)
__global__ void k_scatbuild(const int* __restrict__ off1, const int* __restrict__ par1, int n1,
                            const int* __restrict__ off2, const int* __restrict__ par2, int n2,
                            int* perm1, int* perm2,
                            const int* __restrict__ st1, const int* __restrict__ cnt1,
                            const int* __restrict__ st2, const int* __restrict__ cnt2,
                            int n1p, int n2p,
                            const float* __restrict__ T2, const float* __restrict__ W1,
                            const float* __restrict__ T3, const float* __restrict__ W2,
                            __half* B2h, __half* B3h, int scatBlocks, int buildBlocks) {
    int bid = blockIdx.x;
    if (bid < scatBlocks) {
        int i = bid * blockDim.x + threadIdx.x;
        if (i < n1) {
            int p = atomicAdd(&g_bst[bkt1(off1[i], par1[i])], 1);
            perm1[p] = i;
        } else if (i < n1 + n2) {
            int ii = i - n1;
            int p = atomicAdd(&g_bst[bkt2(off2[ii], par2[ii])], 1);
            perm2[p] = ii;
        }
    } else if (bid < scatBlocks + buildBlocks) {
        int idx = (bid - scatBlocks) * blockDim.x + threadIdx.x;
        const int NB3 = 8 * 256 * 128;
        if (idx < NB3) {
            int bin = idx / (256 * 128);
            int k = (idx >> 7) % 256;
            int n = idx & 127;
            float v = (k < 128) ? T3[((size_t)bin * 128 + k) * 128 + n] : W2[(size_t)(k - 128) * 128 + n];
            int ch = k >> 5, kc = k & 31;
            B3h[(bin * 8 + ch) * 4096 + swz_pos(n, kc)] = __float2half_rn(v);
        } else {
            idx -= NB3;
            if (idx >= 8 * 192 * 128) return;
            int bin = idx / (192 * 128);
            int k = (idx >> 7) % 192;
            int n = idx & 127;
            float v = (k < 128) ? T2[((size_t)bin * 128 + k) * 128 + n] : W1[(size_t)(k - 128) * 128 + n];
            int ch = k >> 5, kc = k & 31;
            B2h[(bin * 6 + ch) * 4096 + swz_pos(n, kc)] = __float2half_rn(v);
        }
    } else {
        // pad-fill block: -1 into tile-padding slots of both perms
        for (int k = 0; k < 8; k++) {
            int lo = st1[k] + cnt1[k], hi = st1[k + 1];
            for (int j = lo + (int)threadIdx.x; j < hi; j += blockDim.x) perm1[j] = -1;
            lo = st2[k] + cnt2[k]; hi = st2[k + 1];
            for (int j = lo + (int)threadIdx.x; j < hi; j += blockDim.x) perm2[j] = -1;
        }
        for (int j = st1[8] + (int)threadIdx.x; j < n1p; j += blockDim.x) perm1[j] = -1;
        for (int j = st2[8] + (int)threadIdx.x; j < n2p; j += blockDim.x) perm2[j] = -1;
    }
}

// ---------------- main gather-GEMM (fp16 mma.sync m16n8k16, 4-stage pipe) ----------------
// dynamic smem 64KB: A[4][8KB] at 0, B[4][8KB] at 32768
// A staging: 4 threads per row (seg = tid&3, 16B each) -> coalesced 64B row gathers
#define SMEM_DYN 65536
template <int KTOT, int CSRC, int CFINE, bool DENSE, bool HC, bool HO>
__global__ __launch_bounds__(NTHR, 2) void k_gemm(
    const void* __restrict__ coarse_, const float* __restrict__ fine,
    const __half* __restrict__ Btiles, const int* __restrict__ perm,
    const int* __restrict__ parent, const int* __restrict__ starts,
    int nrows, int tile0, void* __restrict__ out_)
{
    constexpr int NC = KTOT / 32;
    constexpr int NCC = HC ? (CSRC / 32) : 0;   // chunks staged via cp.async (fp16 coarse)
    constexpr int CEB = HC ? 2 : 4;             // coarse element bytes
    extern __shared__ char smemc[];
    __shared__ int s_gid[TM];
    __shared__ const char* s_pc[TM];
    __shared__ const float* s_pf[TM];
    __shared__ int s_starts[9];

    const int tid = threadIdx.x;
    const int base = (tile0 + blockIdx.x) * TM;

    if (DENSE) {
        if (tid < TM) {
            int gid = (base + tid < nrows) ? base + tid : -1;
            s_gid[tid] = gid;
            s_pc[tid] = (gid >= 0) ? (const char*)coarse_ + (size_t)gid * CSRC * CEB : nullptr;
        }
    } else {
        if (tid < 9) s_starts[tid] = starts[tid];
        if (tid < TM) {
            int gd = perm[base + tid];
            s_gid[tid] = gd;
            s_pc[tid] = (gd >= 0) ? (const char*)coarse_ + (size_t)parent[gd] * CSRC * CEB : nullptr;
            s_pf[tid] = (gd >= 0) ? fine + (size_t)gd * CFINE : nullptr;
        }
    }
    __syncthreads();

    const __half* Bt = Btiles;
    if (!DENSE) {
        if (base >= s_starts[8]) return;
        int kb = 0;
        while (kb < 7 && base >= s_starts[kb + 1]) kb++;
        Bt = Btiles + (size_t)kb * NC * 4096;
    }

    const uint32_t uA = smem_u32(smemc);
    const uint32_t uB = uA + 32768;

    // ---- staging ids: 4 threads per row, seg q = tid&3 (16B units); rows r0, r0+64 ----
    const int q = tid & 3;
    const int r0 = tid >> 2, r1 = r0 + 64;
    const char* pcA = s_pc[r0];
    const char* pcB = s_pc[r1];
    const float* pfA = DENSE ? nullptr : s_pf[r0];
    const float* pfB = DENSE ? nullptr : s_pf[r1];
    const uint32_t cszA = pcA ? 16u : 0u;
    const uint32_t cszB = pcB ? 16u : 0u;
    const uint32_t stsA = r0 * 64 + (((q ^ ((r0 >> 1) & 3))) << 4);
    const uint32_t stsB = r1 * 64 + (((q ^ ((r1 >> 1) & 3))) << 4);

    // ---- compute-lane fragment addressing ----
    const int warp = tid >> 5, lane = tid & 31;
    const int wm = warp & 1, wn = warp >> 1;
    const int alrow = (lane & 7) + ((lane >> 3) & 1) * 8;
    const int akb = lane >> 4;                 // 0/1 k-block offset
    uint32_t a_row[4]; int a_rx[4];
#pragma unroll
    for (int mt = 0; mt < 4; mt++) {
        int r = wm * 64 + mt * 16 + alrow;
        a_row[mt] = uA + r * 64;
        a_rx[mt] = (r >> 1) & 3;
    }
    const int blrow = (lane & 7) + ((lane >> 4) << 3);
    const int bkb = (lane >> 3) & 1;
    uint32_t b_row[2]; int b_rx[2];
#pragma unroll
    for (int p = 0; p < 2; p++) {
        int n = wn * 32 + p * 16 + blrow;
        b_row[p] = uB + n * 64;
        b_rx[p] = (n >> 1) & 3;
    }

    // fp32 staging regs: 2 rows x 2 float4 (32B per row-chunk-seg)
    float4 va0, va1, vb0, vb1;

    // A chunk c via cp.async (fp16 coarse rows; coalesced 4 threads/row)
#define CPA(c) { \
        char* ab = smemc + (uint32_t)((c) & 3) * 8192u; \
        const __half* sA = (const __half*)pcA + (c) * 32 + q * 8; \
        const __half* sB = (const __half*)pcB + (c) * 32 + q * 8; \
        cp16z(ab + stsA, pcA ? (const void*)sA : (const void*)Bt, cszA); \
        cp16z(ab + stsB, pcB ? (const void*)sB : (const void*)Bt, cszB); }

    // B chunk c via cp.async (contiguous, L2-only)
#define CPB(c) { \
        const char* bs = (const char*)Bt + (size_t)(c) * 8192; \
        char* bd = smemc + 32768 + (uint32_t)((c) & 3) * 8192u; \
        cp16cg(bd + tid * 32, bs + tid * 32); \
        cp16cg(bd + tid * 32 + 16, bs + tid * 32 + 16); }

    // fp32 staging: LDG to regs; thread covers floats [q*8, q*8+8) of each row's chunk
#define LDGA(c) { \
        const int kk = (c) * 32 + q * 8; \
        const float* sp; \
        if (!HC) sp = pcA ? (const float*)pcA + kk : nullptr; \
        else     sp = pfA ? pfA + (kk - CSRC) : nullptr; \
        if (sp) { va0 = *(const float4*)sp; va1 = *(const float4*)(sp + 4); } \
        else { va0 = va1 = make_float4(0.f, 0.f, 0.f, 0.f); } \
        if (!HC) sp = pcB ? (const float*)pcB + kk : nullptr; \
        else     sp = pfB ? pfB + (kk - CSRC) : nullptr; \
        if (sp) { vb0 = *(const float4*)sp; vb1 = *(const float4*)(sp + 4); } \
        else { vb0 = vb1 = make_float4(0.f, 0.f, 0.f, 0.f); } }

#define STSA(c) { \
        char* ab = smemc + (uint32_t)((c) & 3) * 8192u; \
        uint4 w0 = make_uint4(pk(va0.x, va0.y), pk(va0.z, va0.w), \
                              pk(va1.x, va1.y), pk(va1.z, va1.w)); \
        uint4 w1 = make_uint4(pk(vb0.x, vb0.y), pk(vb0.z, vb0.w), \
                              pk(vb1.x, vb1.y), pk(vb1.z, vb1.w)); \
        *(uint4*)(ab + stsA) = w0; \
        *(uint4*)(ab + stsB) = w1; }

    // ---- prologue: issue copy groups for chunks 0,1,2 ----
#pragma unroll
    for (int k = 0; k < 3; k++) {
        if (k < NC) {
            if (k < NCC) { CPA(k); }
            else if (k == 0) { LDGA(0); }
            CPB(k);
            cp_commit();
        }
    }

    float acc[4][4][4] = {};

#pragma unroll
    for (int c = 0; c < NC; c++) {
        const uint32_t boff = (uint32_t)(c & 3) * 8192u;
        if (c >= NCC) STSA(c);                       // fp32 chunk: regs -> smem
        if (c + 1 < NC && c + 1 >= NCC) LDGA(c + 1); // prefetch next fp32 chunk
        if (c + 2 < NC) cp_wait2();                  // group c complete
        else if (c + 1 < NC) cp_wait1();
        else cp_wait0();
        __syncthreads();
        if (c + 3 < NC) {                            // issue chunk c+3 group
            if (c + 3 < NCC) CPA(c + 3);
            CPB(c + 3);
            cp_commit();
        }
        // ---- compute chunk c: 12 ldmatrix.x4 + 32 mma per warp ----
#pragma unroll
        for (int kb16 = 0; kb16 < 2; kb16++) {
            const int klo = kb16 * 2;
            uint32_t bf[2][4];
#pragma unroll
            for (int p = 0; p < 2; p++)
                ldsm4(bf[p], b_row[p] + boff + (((klo + bkb) ^ b_rx[p]) << 4));
#pragma unroll
            for (int mt = 0; mt < 4; mt++) {
                uint32_t af[4];
                ldsm4(af, a_row[mt] + boff + (((klo + akb) ^ a_rx[mt]) << 4));
#pragma unroll
                for (int nt = 0; nt < 4; nt++)
                    mma_f16(acc[mt][nt], af, &bf[nt >> 1][(nt & 1) * 2]);
            }
        }
    }

    // ---- epilogue: stage tile through smem -> fully coalesced STG.128 ----
    __syncthreads();                       // mainloop done; buffers reusable
    const int g = lane >> 2, tg = lane & 3;
    if (HO) {
        // fp16 tile: 128 rows x 272B (256B data + 16B pad), single pass
        __half* oh = (__half*)out_;
        uint32_t* sw = (uint32_t*)smemc;
#pragma unroll
        for (int mt = 0; mt < 4; mt++) {
#pragma unroll
            for (int nt = 0; nt < 4; nt++) {
                int col2 = (wn * 32 + nt * 8 + tg * 2) >> 1;
                int r = wm * 64 + mt * 16 + g;
                sw[r * 68 + col2]       = pk(acc[mt][nt][0], acc[mt][nt][1]);
                sw[(r + 8) * 68 + col2] = pk(acc[mt][nt][2], acc[mt][nt][3]);
            }
        }
        __syncthreads();
#pragma unroll
        for (int it = 0; it < 8; it++) {
            int slot = tid + it * 256;
            int lr = slot >> 4, seg = slot & 15;
            int gid = s_gid[lr];
            if (gid >= 0)
                *(uint4*)(oh + (size_t)gid * DD + seg * 8) =
                    *(const uint4*)(smemc + lr * 272 + seg * 16);
        }
    } else {
        // fp32 tile: two passes of 64 rows x 544B (512B data + 32B pad)
        float* of = (float*)out_;
        float* sf = (float*)smemc;
#pragma unroll
        for (int half = 0; half < 2; half++) {
            if (wm == half) {
#pragma unroll
                for (int mt = 0; mt < 4; mt++) {
#pragma unroll
                    for (int nt = 0; nt < 4; nt++) {
                        int col = wn * 32 + nt * 8 + tg * 2;
                        int lr = mt * 16 + g;
                        *(float2*)(sf + lr * 136 + col) =
                            make_float2(acc[mt][nt][0], acc[mt][nt][1]);
                        *(float2*)(sf + (lr + 8) * 136 + col) =
                            make_float2(acc[mt][nt][2], acc[mt][nt][3]);
                    }
                }
            }
            __syncthreads();
#pragma unroll
            for (int it = 0; it < 8; it++) {
                int slot = tid + it * 256;
                int lr = slot >> 5, seg = slot & 31;
                int gid = s_gid[half * 64 + lr];
                if (gid >= 0)
                    *(uint4*)(of + (size_t)gid * DD + seg * 4) =
                        *(const uint4*)(smemc + lr * 544 + seg * 16);
            }
            if (half == 0) __syncthreads();
        }
    }
#undef CPA
#undef CPB
#undef LDGA
#undef STSA
}

// ---------------- launch ----------------
extern "C" void kernel_launch(void* const* d_in, const int* in_sizes, int n_in,
                              void* d_out, int out_size)
{
    const float* feats1  = (const float*)d_in[0];
    const float* feats2  = (const float*)d_in[1];
    const float* feats3  = (const float*)d_in[2];
    const int*   parent1 = (const int*)d_in[3];
    const int*   offset1 = (const int*)d_in[4];
    const int*   parent2 = (const int*)d_in[5];
    const int*   offset2 = (const int*)d_in[6];
    const float* W1 = (const float*)d_in[7];
    const float* W2 = (const float*)d_in[8];
    const float* W3 = (const float*)d_in[9];
    const float* T2 = (const float*)d_in[10];
    const float* T3 = (const float*)d_in[11];

    const int N1 = in_sizes[3];
    const int N2 = in_sizes[5];
    const int N3 = in_sizes[2] / C3;

    __half *y2h, *y3h, *B2h, *B3h, *Bw3h;
    int *perm1, *perm2, *st1, *st2, *cn1, *cn2;
    cudaGetSymbolAddress((void**)&y2h, g_y2h);
    cudaGetSymbolAddress((void**)&y3h, g_y3h);
    cudaGetSymbolAddress((void**)&B2h, g_B2h);
    cudaGetSymbolAddress((void**)&B3h, g_B3h);
    cudaGetSymbolAddress((void**)&Bw3h, g_Bw3h);
    cudaGetSymbolAddress((void**)&perm1, g_perm1);
    cudaGetSymbolAddress((void**)&perm2, g_perm2);
    cudaGetSymbolAddress((void**)&st1, g_st1);
    cudaGetSymbolAddress((void**)&st2, g_st2);
    cudaGetSymbolAddress((void**)&cn1, g_cnt1);
    cudaGetSymbolAddress((void**)&cn2, g_cnt2);

    cudaFuncSetAttribute(k_gemm<256, C3, 1, true, false, true>,
                         cudaFuncAttributeMaxDynamicSharedMemorySize, SMEM_DYN);
    cudaFuncSetAttribute(k_gemm<256, C2, C2, false, true, true>,
                         cudaFuncAttributeMaxDynamicSharedMemorySize, SMEM_DYN);
    cudaFuncSetAttribute(k_gemm<192, C2, C1, false, true, false>,
                         cudaFuncAttributeMaxDynamicSharedMemorySize, SMEM_DYN);

    const int tiles1 = (N1 + TM - 1) / TM + 8;
    const int tiles2 = (N2 + TM - 1) / TM + 8;
    const int n1p = tiles1 * TM;
    const int n2p = tiles2 * TM;
    const int tiles3 = (N3 + TM - 1) / TM;
    const int scatBlocks = (N1 + N2 + 255) / 256;
    const int buildBlocks = (8 * 256 * 128 + 8 * 192 * 128) / 256;   // 1792

    // launch 1: W3 tiles + bucket hist + fused scan (last block)
    k_prep<<<512, 256>>>(offset1, parent1, N1, offset2, parent2, N2,
                         W3, Bw3h, st1, cn1, st2, cn2);
    // launch 2: bucket-clustered scatter + build B tiles + pad-fill (merged)
    k_scatbuild<<<scatBlocks + buildBlocks + 1, 256>>>(offset1, parent1, N1,
        offset2, parent2, N2, perm1, perm2, st1, cn1, st2, cn2, n1p, n2p,
        T2, W1, T3, W2, B2h, B3h, scatBlocks, buildBlocks);
    // launch 3: y3 = feats3 @ W3 -> fp16
    k_gemm<256, C3, 1, true, false, true><<<tiles3, NTHR, SMEM_DYN>>>(feats3, nullptr, Bw3h,
        nullptr, nullptr, nullptr, N3, 0, y3h);
    // launch 4 (ncu capture slot): y2 = gather_tconv(y3, T3) + feats2 @ W2 -> fp16
    k_gemm<256, C2, C2, false, true, true><<<tiles2, NTHR, SMEM_DYN>>>(y3h, feats2, B3h,
        perm2, parent2, st2, 0, 0, y2h);
    // launch 5: out = gather_tconv(y2, T2) + feats1 @ W1 -> fp32
    k_gemm<192, C2, C1, false, true, false><<<tiles1, NTHR, SMEM_DYN>>>(y2h, feats1, B2h,
        perm1, parent1, st1, 0, 0, d_out);
}

// round 17
// speedup vs baseline: 1.4471x; 1.4471x over previous
#include <cuda_runtime.h>
#include <cuda_fp16.h>
#include <cstdint>

#define C1 64
#define C2 128
#define C3 256
#define DD 128
#define TM 128
#define NTHR 256

// ---------------- static device scratch (no allocs allowed) ----------------
__device__ __half g_y2h[(size_t)131072 * DD];    // level-2 merged features (fp16)
__device__ __half g_y3h[(size_t)30720 * DD];     // y3 = feats3 @ W3 (fp16)
__device__ int    g_perm1[420000 + 4096];
__device__ int    g_perm2[131072 + 4096];
__device__ __half g_B3h[8 * 8 * 4096];           // [bin][chunk][n][k swizzled] fp16
__device__ __half g_B2h[8 * 6 * 4096];
__device__ __half g_Bw3h[8 * 4096];              // W3 chunks for y3 GEMM
__device__ int    g_hpart[512 * 16];             // per-block hist partials
__device__ int    g_done;                        // prep completion counter
__device__ int    g_st1[9], g_st2[9];
__device__ int    g_cnt1[8], g_cnt2[8];
__device__ int    g_cur1[8], g_cur2[8];

// ---------------- helpers ----------------
__device__ __forceinline__ uint32_t smem_u32(const void* p) {
    uint32_t a;
    asm("{ .reg .u64 t; cvta.to.shared.u64 t, %1; cvt.u32.u64 %0, t; }" : "=r"(a) : "l"(p));
    return a;
}
// B staging: L2-only (cg) — B is read once per CTA and shared via L2; keep it out of L1
__device__ __forceinline__ void cp16cg(void* dst_smem, const void* src) {
    uint32_t d = smem_u32(dst_smem);
    asm volatile("cp.async.cg.shared.global [%0], [%1], 16;" :: "r"(d), "l"(src) : "memory");
}
// A gather: L1-cached (ca) with zero-fill; gather lines have cross-chunk reuse in L1
__device__ __forceinline__ void cp16z(void* dst_smem, const void* src, uint32_t srcsize) {
    uint32_t d = smem_u32(dst_smem);
    asm volatile("cp.async.ca.shared.global [%0], [%1], 16, %2;"
                 :: "r"(d), "l"(src), "r"(srcsize) : "memory");
}
__device__ __forceinline__ void cp_commit() { asm volatile("cp.async.commit_group;" ::: "memory"); }
__device__ __forceinline__ void cp_wait2()  { asm volatile("cp.async.wait_group 2;" ::: "memory"); }
__device__ __forceinline__ void cp_wait1()  { asm volatile("cp.async.wait_group 1;" ::: "memory"); }
__device__ __forceinline__ void cp_wait0()  { asm volatile("cp.async.wait_group 0;" ::: "memory"); }

__device__ __forceinline__ uint32_t pk(float a, float b) {
    __half2 h = __floats2half2_rn(a, b);
    return *(uint32_t*)&h;
}
__device__ __forceinline__ void ldsm4(uint32_t* r, uint32_t addr) {
    asm volatile("ldmatrix.sync.aligned.m8n8.x4.shared.b16 {%0,%1,%2,%3}, [%4];"
                 : "=r"(r[0]), "=r"(r[1]), "=r"(r[2]), "=r"(r[3]) : "r"(addr));
}
__device__ __forceinline__ void mma_f16(float* c, const uint32_t* a, const uint32_t* b) {
    asm volatile(
        "mma.sync.aligned.m16n8k16.row.col.f32.f16.f16.f32 "
        "{%0,%1,%2,%3}, {%4,%5,%6,%7}, {%8,%9}, {%0,%1,%2,%3};\n"
        : "+f"(c[0]), "+f"(c[1]), "+f"(c[2]), "+f"(c[3])
        : "r"(a[0]), "r"(a[1]), "r"(a[2]), "r"(a[3]), "r"(b[0]), "r"(b[1]));
}

// swizzled half-index within a row-chunk tile (rows of 64B, XOR on 16B blocks)
__device__ __forceinline__ int swz_pos(int row, int kc) {
    return row * 32 + ((((kc >> 3) & 3) ^ ((row >> 1) & 3)) << 3) + (kc & 7);
}

// ---------------- prep: W3 fp16 tiles + hist partials + fused last-block scan ----------------
__global__ void k_prep(const int* __restrict__ off1, int n1,
                       const int* __restrict__ off2, int n2, int* hpart,
                       const float* __restrict__ W3, __half* Bw3h,
                       int* st1, int* cnt1, int* cur1,
                       int* st2, int* cnt2, int* cur2) {
    __shared__ int s[16];
    __shared__ int s_last;
    if (threadIdx.x < 16) s[threadIdx.x] = 0;
    __syncthreads();
    int i = blockIdx.x * blockDim.x + threadIdx.x;
    int stride = gridDim.x * blockDim.x;
    for (int j = i; j < 256 * 128; j += stride) {
        int k = j >> 7, n = j & 127;
        int ch = k >> 5, kc = k & 31;
        Bw3h[ch * 4096 + swz_pos(n, kc)] = __float2half_rn(W3[(size_t)k * 128 + n]);
    }
    for (int j = i; j < n1; j += stride) atomicAdd(&s[off1[j]], 1);
    for (int j = i; j < n2; j += stride) atomicAdd(&s[8 + off2[j]], 1);
    __syncthreads();
    if (threadIdx.x < 16) atomicExch(&hpart[blockIdx.x * 16 + threadIdx.x], s[threadIdx.x]);
    __syncthreads();
    if (threadIdx.x == 0) {
        __threadfence();
        s_last = (atomicAdd(&g_done, 1) == (int)gridDim.x - 1) ? 1 : 0;
    }
    __syncthreads();
    if (s_last) {
        __threadfence();
        __shared__ int c[16];
        if (threadIdx.x < 16) c[threadIdx.x] = 0;
        __syncthreads();
        int bin = threadIdx.x & 15, slice = threadIdx.x >> 4;
        int sum = 0;
        for (int b = slice; b < (int)gridDim.x; b += 16) sum += hpart[b * 16 + bin];
        atomicAdd(&c[bin], sum);
        __syncthreads();
        if (threadIdx.x == 0) {
            int run = 0;
            for (int k = 0; k < 8; k++) {
                st1[k] = run; cur1[k] = run; cnt1[k] = c[k];
                run += ((c[k] + TM - 1) / TM) * TM;
            }
            st1[8] = run;
            run = 0;
            for (int k = 0; k < 8; k++) {
                st2[k] = run; cur2[k] = run; cnt2[k] = c[8 + k];
                run += ((c[8 + k] + TM - 1) / TM) * TM;
            }
            st2[8] = run;
            g_done = 0;                 // reset for next graph replay
        }
    }
}

// merged: scatter perms + build fp16 B tiles + pad-fill (last block)
__global__ void k_scatbuild(const int* __restrict__ off1, int n1,
                            const int* __restrict__ off2, int n2,
                            int* cur1, int* cur2, int* perm1, int* perm2,
                            const int* __restrict__ st1, const int* __restrict__ cnt1,
                            const int* __restrict__ st2, const int* __restrict__ cnt2,
                            int n1p, int n2p,
                            const float* __restrict__ T2, const float* __restrict__ W1,
                            const float* __restrict__ T3, const float* __restrict__ W2,
                            __half* B2h, __half* B3h, int scatBlocks, int buildBlocks) {
    int bid = blockIdx.x;
    if (bid < scatBlocks) {
        __shared__ int s_cnt[16], s_base[16];
        int i = bid * blockDim.x + threadIdx.x;
        if (threadIdx.x < 16) s_cnt[threadIdx.x] = 0;
        __syncthreads();
        int slot = -1, r = 0;
        if (i < n1)           { slot = off1[i];          r = atomicAdd(&s_cnt[slot], 1); }
        else if (i < n1 + n2) { slot = 8 + off2[i - n1]; r = atomicAdd(&s_cnt[slot], 1); }
        __syncthreads();
        if (threadIdx.x < 16) {
            int c = s_cnt[threadIdx.x];
            if (c) s_base[threadIdx.x] = (threadIdx.x < 8)
                ? atomicAdd(&cur1[threadIdx.x], c) : atomicAdd(&cur2[threadIdx.x - 8], c);
        }
        __syncthreads();
        if (slot >= 0) {
            if (slot < 8) perm1[s_base[slot] + r] = i;
            else          perm2[s_base[slot] + r] = i - n1;
        }
    } else if (bid < scatBlocks + buildBlocks) {
        int idx = (bid - scatBlocks) * blockDim.x + threadIdx.x;
        const int NB3 = 8 * 256 * 128;
        if (idx < NB3) {
            int bin = idx / (256 * 128);
            int k = (idx >> 7) % 256;
            int n = idx & 127;
            float v = (k < 128) ? T3[((size_t)bin * 128 + k) * 128 + n] : W2[(size_t)(k - 128) * 128 + n];
            int ch = k >> 5, kc = k & 31;
            B3h[(bin * 8 + ch) * 4096 + swz_pos(n, kc)] = __float2half_rn(v);
        } else {
            idx -= NB3;
            if (idx >= 8 * 192 * 128) return;
            int bin = idx / (192 * 128);
            int k = (idx >> 7) % 192;
            int n = idx & 127;
            float v = (k < 128) ? T2[((size_t)bin * 128 + k) * 128 + n] : W1[(size_t)(k - 128) * 128 + n];
            int ch = k >> 5, kc = k & 31;
            B2h[(bin * 6 + ch) * 4096 + swz_pos(n, kc)] = __float2half_rn(v);
        }
    } else {
        // pad-fill block: -1 into tile-padding slots of both perms
        for (int k = 0; k < 8; k++) {
            int lo = st1[k] + cnt1[k], hi = st1[k + 1];
            for (int j = lo + (int)threadIdx.x; j < hi; j += blockDim.x) perm1[j] = -1;
            lo = st2[k] + cnt2[k]; hi = st2[k + 1];
            for (int j = lo + (int)threadIdx.x; j < hi; j += blockDim.x) perm2[j] = -1;
        }
        for (int j = st1[8] + (int)threadIdx.x; j < n1p; j += blockDim.x) perm1[j] = -1;
        for (int j = st2[8] + (int)threadIdx.x; j < n2p; j += blockDim.x) perm2[j] = -1;
    }
}

// ---------------- main gather-GEMM (fp16 mma.sync m16n8k16, 4-stage pipe) ----------------
// dynamic smem 64KB: A[4][8KB] at 0, B[4][8KB] at 32768
// A staging: 4 threads per row (seg = tid&3, 16B each) -> coalesced 64B row gathers
#define SMEM_DYN 65536
template <int KTOT, int CSRC, int CFINE, bool DENSE, bool HC, bool HO>
__global__ __launch_bounds__(NTHR, 2) void k_gemm(
    const void* __restrict__ coarse_, const float* __restrict__ fine,
    const __half* __restrict__ Btiles, const int* __restrict__ perm,
    const int* __restrict__ parent, const int* __restrict__ starts,
    int nrows, int tile0, void* __restrict__ out_)
{
    constexpr int NC = KTOT / 32;
    constexpr int NCC = HC ? (CSRC / 32) : 0;   // chunks staged via cp.async (fp16 coarse)
    constexpr int CEB = HC ? 2 : 4;             // coarse element bytes
    extern __shared__ char smemc[];
    __shared__ int s_gid[TM];
    __shared__ const char* s_pc[TM];
    __shared__ const float* s_pf[TM];
    __shared__ int s_starts[9];

    const int tid = threadIdx.x;
    const int base = (tile0 + blockIdx.x) * TM;

    if (DENSE) {
        if (tid < TM) {
            int gid = (base + tid < nrows) ? base + tid : -1;
            s_gid[tid] = gid;
            s_pc[tid] = (gid >= 0) ? (const char*)coarse_ + (size_t)gid * CSRC * CEB : nullptr;
        }
    } else {
        if (tid < 9) s_starts[tid] = starts[tid];
        if (tid < TM) {
            int gd = perm[base + tid];
            s_gid[tid] = gd;
            s_pc[tid] = (gd >= 0) ? (const char*)coarse_ + (size_t)parent[gd] * CSRC * CEB : nullptr;
            s_pf[tid] = (gd >= 0) ? fine + (size_t)gd * CFINE : nullptr;
        }
    }
    __syncthreads();

    const __half* Bt = Btiles;
    if (!DENSE) {
        if (base >= s_starts[8]) return;
        int kb = 0;
        while (kb < 7 && base >= s_starts[kb + 1]) kb++;
        Bt = Btiles + (size_t)kb * NC * 4096;
    }

    const uint32_t uA = smem_u32(smemc);
    const uint32_t uB = uA + 32768;

    // ---- staging ids: 4 threads per row, seg q = tid&3 (16B units); rows r0, r0+64 ----
    const int q = tid & 3;
    const int r0 = tid >> 2, r1 = r0 + 64;
    const char* pcA = s_pc[r0];
    const char* pcB = s_pc[r1];
    const float* pfA = DENSE ? nullptr : s_pf[r0];
    const float* pfB = DENSE ? nullptr : s_pf[r1];
    const uint32_t cszA = pcA ? 16u : 0u;
    const uint32_t cszB = pcB ? 16u : 0u;
    const uint32_t stsA = r0 * 64 + (((q ^ ((r0 >> 1) & 3))) << 4);
    const uint32_t stsB = r1 * 64 + (((q ^ ((r1 >> 1) & 3))) << 4);

    // ---- compute-lane fragment addressing ----
    const int warp = tid >> 5, lane = tid & 31;
    const int wm = warp & 1, wn = warp >> 1;
    const int alrow = (lane & 7) + ((lane >> 3) & 1) * 8;
    const int akb = lane >> 4;                 // 0/1 k-block offset
    uint32_t a_row[4]; int a_rx[4];
#pragma unroll
    for (int mt = 0; mt < 4; mt++) {
        int r = wm * 64 + mt * 16 + alrow;
        a_row[mt] = uA + r * 64;
        a_rx[mt] = (r >> 1) & 3;
    }
    const int blrow = (lane & 7) + ((lane >> 4) << 3);
    const int bkb = (lane >> 3) & 1;
    uint32_t b_row[2]; int b_rx[2];
#pragma unroll
    for (int p = 0; p < 2; p++) {
        int n = wn * 32 + p * 16 + blrow;
        b_row[p] = uB + n * 64;
        b_rx[p] = (n >> 1) & 3;
    }

    // fp32 staging regs: 2 rows x 2 float4 (32B per row-chunk-seg)
    float4 va0, va1, vb0, vb1;

    // A chunk c via cp.async (fp16 coarse rows; coalesced 4 threads/row)
#define CPA(c) { \
        char* ab = smemc + (uint32_t)((c) & 3) * 8192u; \
        const __half* sA = (const __half*)pcA + (c) * 32 + q * 8; \
        const __half* sB = (const __half*)pcB + (c) * 32 + q * 8; \
        cp16z(ab + stsA, pcA ? (const void*)sA : (const void*)Bt, cszA); \
        cp16z(ab + stsB, pcB ? (const void*)sB : (const void*)Bt, cszB); }

    // B chunk c via cp.async (contiguous, L2-only)
#define CPB(c) { \
        const char* bs = (const char*)Bt + (size_t)(c) * 8192; \
        char* bd = smemc + 32768 + (uint32_t)((c) & 3) * 8192u; \
        cp16cg(bd + tid * 32, bs + tid * 32); \
        cp16cg(bd + tid * 32 + 16, bs + tid * 32 + 16); }

    // fp32 staging: LDG to regs; thread covers floats [q*8, q*8+8) of each row's chunk
#define LDGA(c) { \
        const int kk = (c) * 32 + q * 8; \
        const float* sp; \
        if (!HC) sp = pcA ? (const float*)pcA + kk : nullptr; \
        else     sp = pfA ? pfA + (kk - CSRC) : nullptr; \
        if (sp) { va0 = *(const float4*)sp; va1 = *(const float4*)(sp + 4); } \
        else { va0 = va1 = make_float4(0.f, 0.f, 0.f, 0.f); } \
        if (!HC) sp = pcB ? (const float*)pcB + kk : nullptr; \
        else     sp = pfB ? pfB + (kk - CSRC) : nullptr; \
        if (sp) { vb0 = *(const float4*)sp; vb1 = *(const float4*)(sp + 4); } \
        else { vb0 = vb1 = make_float4(0.f, 0.f, 0.f, 0.f); } }

#define STSA(c) { \
        char* ab = smemc + (uint32_t)((c) & 3) * 8192u; \
        uint4 w0 = make_uint4(pk(va0.x, va0.y), pk(va0.z, va0.w), \
                              pk(va1.x, va1.y), pk(va1.z, va1.w)); \
        uint4 w1 = make_uint4(pk(vb0.x, vb0.y), pk(vb0.z, vb0.w), \
                              pk(vb1.x, vb1.y), pk(vb1.z, vb1.w)); \
        *(uint4*)(ab + stsA) = w0; \
        *(uint4*)(ab + stsB) = w1; }

    // ---- prologue: issue copy groups for chunks 0,1,2 ----
#pragma unroll
    for (int k = 0; k < 3; k++) {
        if (k < NC) {
            if (k < NCC) { CPA(k); }
            else if (k == 0) { LDGA(0); }
            CPB(k);
            cp_commit();
        }
    }

    float acc[4][4][4] = {};

#pragma unroll
    for (int c = 0; c < NC; c++) {
        const uint32_t boff = (uint32_t)(c & 3) * 8192u;
        if (c >= NCC) STSA(c);                       // fp32 chunk: regs -> smem
        if (c + 1 < NC && c + 1 >= NCC) LDGA(c + 1); // prefetch next fp32 chunk
        if (c + 2 < NC) cp_wait2();                  // group c complete
        else if (c + 1 < NC) cp_wait1();
        else cp_wait0();
        __syncthreads();
        if (c + 3 < NC) {                            // issue chunk c+3 group
            if (c + 3 < NCC) CPA(c + 3);
            CPB(c + 3);
            cp_commit();
        }
        // ---- compute chunk c: 12 ldmatrix.x4 + 32 mma per warp ----
#pragma unroll
        for (int kb16 = 0; kb16 < 2; kb16++) {
            const int klo = kb16 * 2;
            uint32_t bf[2][4];
#pragma unroll
            for (int p = 0; p < 2; p++)
                ldsm4(bf[p], b_row[p] + boff + (((klo + bkb) ^ b_rx[p]) << 4));
#pragma unroll
            for (int mt = 0; mt < 4; mt++) {
                uint32_t af[4];
                ldsm4(af, a_row[mt] + boff + (((klo + akb) ^ a_rx[mt]) << 4));
#pragma unroll
                for (int nt = 0; nt < 4; nt++)
                    mma_f16(acc[mt][nt], af, &bf[nt >> 1][(nt & 1) * 2]);
            }
        }
    }

    // ---- epilogue: stage tile through smem -> fully coalesced STG.128 ----
    __syncthreads();                       // mainloop done; buffers reusable
    const int g = lane >> 2, tg = lane & 3;
    if (HO) {
        // fp16 tile: 128 rows x 272B (256B data + 16B pad), single pass
        __half* oh = (__half*)out_;
        uint32_t* sw = (uint32_t*)smemc;
#pragma unroll
        for (int mt = 0; mt < 4; mt++) {
#pragma unroll
            for (int nt = 0; nt < 4; nt++) {
                int col2 = (wn * 32 + nt * 8 + tg * 2) >> 1;
                int r = wm * 64 + mt * 16 + g;
                sw[r * 68 + col2]       = pk(acc[mt][nt][0], acc[mt][nt][1]);
                sw[(r + 8) * 68 + col2] = pk(acc[mt][nt][2], acc[mt][nt][3]);
            }
        }
        __syncthreads();
#pragma unroll
        for (int it = 0; it < 8; it++) {
            int slot = tid + it * 256;
            int lr = slot >> 4, seg = slot & 15;
            int gid = s_gid[lr];
            if (gid >= 0)
                *(uint4*)(oh + (size_t)gid * DD + seg * 8) =
                    *(const uint4*)(smemc + lr * 272 + seg * 16);
        }
    } else {
        // fp32 tile: two passes of 64 rows x 544B (512B data + 32B pad)
        float* of = (float*)out_;
        float* sf = (float*)smemc;
#pragma unroll
        for (int half = 0; half < 2; half++) {
            if (wm == half) {
#pragma unroll
                for (int mt = 0; mt < 4; mt++) {
#pragma unroll
                    for (int nt = 0; nt < 4; nt++) {
                        int col = wn * 32 + nt * 8 + tg * 2;
                        int lr = mt * 16 + g;
                        *(float2*)(sf + lr * 136 + col) =
                            make_float2(acc[mt][nt][0], acc[mt][nt][1]);
                        *(float2*)(sf + (lr + 8) * 136 + col) =
                            make_float2(acc[mt][nt][2], acc[mt][nt][3]);
                    }
                }
            }
            __syncthreads();
#pragma unroll
            for (int it = 0; it < 8; it++) {
                int slot = tid + it * 256;
                int lr = slot >> 5, seg = slot & 31;
                int gid = s_gid[half * 64 + lr];
                if (gid >= 0)
                    *(uint4*)(of + (size_t)gid * DD + seg * 4) =
                        *(const uint4*)(smemc + lr * 544 + seg * 16);
            }
            if (half == 0) __syncthreads();
        }
    }
#undef CPA
#undef CPB
#undef LDGA
#undef STSA
}

// ---------------- launch ----------------
extern "C" void kernel_launch(void* const* d_in, const int* in_sizes, int n_in,
                              void* d_out, int out_size)
{
    const float* feats1  = (const float*)d_in[0];
    const float* feats2  = (const float*)d_in[1];
    const float* feats3  = (const float*)d_in[2];
    const int*   parent1 = (const int*)d_in[3];
    const int*   offset1 = (const int*)d_in[4];
    const int*   parent2 = (const int*)d_in[5];
    const int*   offset2 = (const int*)d_in[6];
    const float* W1 = (const float*)d_in[7];
    const float* W2 = (const float*)d_in[8];
    const float* W3 = (const float*)d_in[9];
    const float* T2 = (const float*)d_in[10];
    const float* T3 = (const float*)d_in[11];

    const int N1 = in_sizes[3];
    const int N2 = in_sizes[5];
    const int N3 = in_sizes[2] / C3;

    __half *y2h, *y3h, *B2h, *B3h, *Bw3h;
    int *perm1, *perm2, *hpart, *st1, *st2, *cn1, *cn2, *cu1, *cu2;
    cudaGetSymbolAddress((void**)&y2h, g_y2h);
    cudaGetSymbolAddress((void**)&y3h, g_y3h);
    cudaGetSymbolAddress((void**)&B2h, g_B2h);
    cudaGetSymbolAddress((void**)&B3h, g_B3h);
    cudaGetSymbolAddress((void**)&Bw3h, g_Bw3h);
    cudaGetSymbolAddress((void**)&perm1, g_perm1);
    cudaGetSymbolAddress((void**)&perm2, g_perm2);
    cudaGetSymbolAddress((void**)&hpart, g_hpart);
    cudaGetSymbolAddress((void**)&st1, g_st1);
    cudaGetSymbolAddress((void**)&st2, g_st2);
    cudaGetSymbolAddress((void**)&cn1, g_cnt1);
    cudaGetSymbolAddress((void**)&cn2, g_cnt2);
    cudaGetSymbolAddress((void**)&cu1, g_cur1);
    cudaGetSymbolAddress((void**)&cu2, g_cur2);

    cudaFuncSetAttribute(k_gemm<256, C3, 1, true, false, true>,
                         cudaFuncAttributeMaxDynamicSharedMemorySize, SMEM_DYN);
    cudaFuncSetAttribute(k_gemm<256, C2, C2, false, true, true>,
                         cudaFuncAttributeMaxDynamicSharedMemorySize, SMEM_DYN);
    cudaFuncSetAttribute(k_gemm<192, C2, C1, false, true, false>,
                         cudaFuncAttributeMaxDynamicSharedMemorySize, SMEM_DYN);

    const int tiles1 = (N1 + TM - 1) / TM + 8;
    const int tiles2 = (N2 + TM - 1) / TM + 8;
    const int n1p = tiles1 * TM;
    const int n2p = tiles2 * TM;
    const int tiles3 = (N3 + TM - 1) / TM;
    const int scatBlocks = (N1 + N2 + 255) / 256;
    const int buildBlocks = (8 * 256 * 128 + 8 * 192 * 128) / 256;   // 1792

    // launch 1: W3 tiles + hist partials + fused scan (last block)
    k_prep<<<512, 256>>>(offset1, N1, offset2, N2, hpart, W3, Bw3h,
                         st1, cn1, cu1, st2, cn2, cu2);
    // launch 2: scatter perms + build B tiles + pad-fill (merged)
    k_scatbuild<<<scatBlocks + buildBlocks + 1, 256>>>(offset1, N1, offset2, N2,
        cu1, cu2, perm1, perm2, st1, cn1, st2, cn2, n1p, n2p,
        T2, W1, T3, W2, B2h, B3h, scatBlocks, buildBlocks);
    // launch 3: y3 = feats3 @ W3 -> fp16
    k_gemm<256, C3, 1, true, false, true><<<tiles3, NTHR, SMEM_DYN>>>(feats3, nullptr, Bw3h,
        nullptr, nullptr, nullptr, N3, 0, y3h);
    // launch 4 (ncu capture slot): y2 = gather_tconv(y3, T3) + feats2 @ W2 -> fp16
    k_gemm<256, C2, C2, false, true, true><<<tiles2, NTHR, SMEM_DYN>>>(y3h, feats2, B3h,
        perm2, parent2, st2, 0, 0, y2h);
    // launch 5: out = gather_tconv(y2, T2) + feats1 @ W1 -> fp32
    k_gemm<192, C2, C1, false, true, false><<<tiles1, NTHR, SMEM_DYN>>>(y2h, feats1, B2h,
        perm1, parent1, st1, 0, 0, d_out);
}